// round 14
// baseline (speedup 1.0000x reference)
#include <cuda_runtime.h>
#include <cuda_fp16.h>
#include <math.h>

#define NROWS   65536
#define DIM     64
#define KC      512
#define NQ      (NROWS*DIM)
#define THREADS 512
#define MTILE   64
#define NTILES  (NROWS/MTILE)    // 1024
#define GRID    148
#define XSS     68               // x-splat row stride (u32)
#define DDELTA  2e-2f
#define SLOTS   24

// smem byte offsets
#define SMO_EH   0                       // fp16 pair image [d][256]: 65536 B
#define SMO_XS   65536                   // 64 x 68 u32 splat-x: 17408 B
#define SMO_SB   82944                   // 512 f32 code norms
#define SMO_SA   84992                   // 64 f32 row norms
#define SMO_KEYS 85248                   // 64 u64 approx-min keys
#define SMO_CNT  85760                   // 64 int
#define SMO_LIST 86016                   // 64 x 24 int
#define SMEM_TOTAL 92160

// Output: [0] loss | [1..NQ] quantized_st (base out+1, 4B-aligned) |
//         [1+NQ] perplexity | [2+NQ..] indices (as float)

typedef unsigned long long ull;

__device__ unsigned g_EH[DIM*256];   // half2 (e[2p][d], e[2p+1][d])
__device__ float    g_sb[KC];
__device__ int      g_hist[KC];
__device__ double   g_sse;
__device__ unsigned g_done;

__device__ __forceinline__ unsigned ord32(float f) {
    unsigned u = __float_as_uint(f);
    return (u & 0x80000000u) ? ~u : (u | 0x80000000u);
}
__device__ __forceinline__ float inv_ord32(unsigned u) {
    return __uint_as_float((u & 0x80000000u) ? (u & 0x7FFFFFFFu) : ~u);
}
__device__ __forceinline__ __half2 h2bits(unsigned u) {
    __half2 h; *reinterpret_cast<unsigned*>(&h) = u; return h;
}
__device__ __forceinline__ unsigned bits_h2(__half2 h) {
    return *reinterpret_cast<unsigned*>(&h);
}
// identical approx-dd in both passes (deterministic)
__device__ __forceinline__ float ddapprox(float tA, float b, float c) {
    float t = tA + b;
    return t - 2.0f * c;
}

// ---- prep: fp16 pair image + exact code norms + zero globals ----------------
__global__ void prep_kernel(const float* __restrict__ emb) {
    int t = blockIdx.x * blockDim.x + threadIdx.x;
    if (t == 0) { g_sse = 0.0; g_done = 0u; }
    if (t < KC) {
        g_hist[t] = 0;
        const float* e = emb + (size_t)t * DIM;
        float b0 = 0.f, b1 = 0.f;
        #pragma unroll
        for (int i = 0; i < DIM; i += 2) {
            b0 = fmaf(e[i],     e[i],     b0);
            b1 = fmaf(e[i + 1], e[i + 1], b1);
        }
        g_sb[t] = b0 + b1;
    }
    if (t < 256) {   // pair p -> codes 2p, 2p+1
        const float* e0 = emb + (size_t)(2 * t) * DIM;
        const float* e1 = emb + (size_t)(2 * t + 1) * DIM;
        for (int d = 0; d < DIM; d++)
            g_EH[d * 256 + t] = bits_h2(__floats2half2_rn(e0[d], e1[d]));
    }
}

// -----------------------------------------------------------------------------
// fp16-filter VQ (512 thr, ~100 regs): 64-row tiles, 8 rows x 4 code-pairs per
// thread, HFMA2 scores; deterministic window DDELTA; exact fp32 recheck:
//   d_k = fl( fl(A + b_k) - 2*c_k ),  tie -> lower k   (validated semantics).
// -----------------------------------------------------------------------------
__global__ void __launch_bounds__(THREADS, 1)
vq_h2_kernel(const float* __restrict__ inp,
             const float* __restrict__ emb,
             float* __restrict__ out)
{
    extern __shared__ char smc[];
    unsigned* EH   = reinterpret_cast<unsigned*>(smc + SMO_EH);
    unsigned* XS   = reinterpret_cast<unsigned*>(smc + SMO_XS);
    float*    sbv  = reinterpret_cast<float*>(smc + SMO_SB);
    float*    sA   = reinterpret_cast<float*>(smc + SMO_SA);
    ull*      keys = reinterpret_cast<ull*>(smc + SMO_KEYS);
    int*      cnt  = reinterpret_cast<int*>(smc + SMO_CNT);
    int*      list = reinterpret_cast<int*>(smc + SMO_LIST);

    const int tid  = threadIdx.x;
    const int lane = tid & 31;
    const int rg   = tid >> 6;    // row-group 0..7 (8 rows)
    const int cg   = tid & 63;    // code-pair lane (pairs cg + 64j)
    const int prow = tid >> 3;    // pro/epilogue row 0..63
    const int part = tid & 7;     // 8 threads per row

    for (int i = tid; i < DIM * 256 / 4; i += THREADS)
        reinterpret_cast<uint4*>(EH)[i] = reinterpret_cast<const uint4*>(g_EH)[i];
    for (int i = tid; i < KC; i += THREADS) sbv[i] = g_sb[i];

    for (int tile = blockIdx.x; tile < NTILES; tile += GRID) {
        __syncthreads();   // prior tile reads of XS/keys/list done

        // ---- prologue: 8 threads/row: splat-dup fp16 x + exact row norm -----
        {
            const int row = tile * MTILE + prow;
            const float4* xp = reinterpret_cast<const float4*>(
                inp + (size_t)row * DIM + part * 8);
            float4 v0 = xp[0], v1 = xp[1];
            float a = 0.f;
            a = fmaf(v0.x, v0.x, a); a = fmaf(v0.y, v0.y, a);
            a = fmaf(v0.z, v0.z, a); a = fmaf(v0.w, v0.w, a);
            a = fmaf(v1.x, v1.x, a); a = fmaf(v1.y, v1.y, a);
            a = fmaf(v1.z, v1.z, a); a = fmaf(v1.w, v1.w, a);
            a += __shfl_xor_sync(0xFFFFFFFFu, a, 1, 8);
            a += __shfl_xor_sync(0xFFFFFFFFu, a, 2, 8);
            a += __shfl_xor_sync(0xFFFFFFFFu, a, 4, 8);
            // A-order argmin-invariant (ULP(64) grid; validated since R2)

            uint4* xd = reinterpret_cast<uint4*>(XS + prow * XSS + part * 8);
            xd[0] = make_uint4(
                bits_h2(__half2half2(__float2half_rn(v0.x))),
                bits_h2(__half2half2(__float2half_rn(v0.y))),
                bits_h2(__half2half2(__float2half_rn(v0.z))),
                bits_h2(__half2half2(__float2half_rn(v0.w))));
            xd[1] = make_uint4(
                bits_h2(__half2half2(__float2half_rn(v1.x))),
                bits_h2(__half2half2(__float2half_rn(v1.y))),
                bits_h2(__half2half2(__float2half_rn(v1.z))),
                bits_h2(__half2half2(__float2half_rn(v1.w))));
            if (part == 0) sA[prow] = a;
            if (tid < MTILE) { keys[tid] = ~0ull; cnt[tid] = 0; }
        }
        __syncthreads();

        // ---- mainloop: acc[r][j] over 8 rows x 4 pairs, d unrolled x4 -------
        __half2 acc[8][4];
        #pragma unroll
        for (int r = 0; r < 8; r++)
            #pragma unroll
            for (int j = 0; j < 4; j++) acc[r][j] = __float2half2_rn(0.f);

        const unsigned* xr = XS + rg * 8 * XSS;
        const unsigned* ec = EH + cg;
        #pragma unroll 2
        for (int d4 = 0; d4 < DIM / 4; d4++) {
            __half2 ev[4][4];                       // [dd][j]
            #pragma unroll
            for (int dd = 0; dd < 4; dd++) {
                const unsigned* Ed = ec + (4 * d4 + dd) * 256;
                #pragma unroll
                for (int j = 0; j < 4; j++)
                    ev[dd][j] = h2bits(Ed[64 * j]);
            }
            uint4 xv[8];
            #pragma unroll
            for (int r = 0; r < 8; r++)             // broadcast LDS.128
                xv[r] = *reinterpret_cast<const uint4*>(xr + r * XSS + 4 * d4);
            #pragma unroll
            for (int r = 0; r < 8; r++) {
                __half2 x0 = h2bits(xv[r].x), x1 = h2bits(xv[r].y);
                __half2 x2 = h2bits(xv[r].z), x3 = h2bits(xv[r].w);
                #pragma unroll
                for (int j = 0; j < 4; j++) {
                    acc[r][j] = __hfma2(x0, ev[0][j], acc[r][j]);
                    acc[r][j] = __hfma2(x1, ev[1][j], acc[r][j]);
                    acc[r][j] = __hfma2(x2, ev[2][j], acc[r][j]);
                    acc[r][j] = __hfma2(x3, ev[3][j], acc[r][j]);
                }
            }
        }

        // ---- pass 1: approx min keys per row --------------------------------
        float2 bb[4];
        #pragma unroll
        for (int j = 0; j < 4; j++)
            bb[j] = *reinterpret_cast<const float2*>(&sbv[2 * (cg + 64 * j)]);
        #pragma unroll
        for (int r = 0; r < 8; r++) {
            float tA = sA[rg * 8 + r];
            ull best = ~0ull;
            #pragma unroll
            for (int j = 0; j < 4; j++) {
                int k0 = 2 * (cg + 64 * j);
                float2 c = __half22float2(acc[r][j]);
                float d0 = ddapprox(tA, bb[j].x, c.x);
                float d1 = ddapprox(tA, bb[j].y, c.y);
                ull key0 = ((ull)ord32(d0) << 32) | (unsigned)k0;
                ull key1 = ((ull)ord32(d1) << 32) | (unsigned)(k0 + 1);
                if (key0 < best) best = key0;
                if (key1 < best) best = key1;
            }
            #pragma unroll
            for (int off = 16; off > 0; off >>= 1) {
                ull o = __shfl_xor_sync(0xFFFFFFFFu, best, off);
                best = (o < best) ? o : best;
            }
            if (lane == 0) atomicMin(&keys[rg * 8 + r], best);
        }
        __syncthreads();

        // ---- pass 2: collect candidates within DDELTA -----------------------
        #pragma unroll
        for (int r = 0; r < 8; r++) {
            int   rr  = rg * 8 + r;
            float tA  = sA[rr];
            float thr = inv_ord32((unsigned)(keys[rr] >> 32)) + DDELTA;
            #pragma unroll
            for (int j = 0; j < 4; j++) {
                int k0 = 2 * (cg + 64 * j);
                float2 c = __half22float2(acc[r][j]);
                float d0 = ddapprox(tA, bb[j].x, c.x);
                float d1 = ddapprox(tA, bb[j].y, c.y);
                if (d0 <= thr) {                       // rare
                    int p = atomicAdd(&cnt[rr], 1);
                    if (p < SLOTS) list[rr * SLOTS + p] = k0;
                }
                if (d1 <= thr) {
                    int p = atomicAdd(&cnt[rr], 1);
                    if (p < SLOTS) list[rr * SLOTS + p] = k0 + 1;
                }
            }
        }
        __syncthreads();

        // ---- exact fp32 recheck + epilogue (8 threads/row) ------------------
        {
            const int row = tile * MTILE + prow;
            const float tA = sA[prow];
            const float4* xp = reinterpret_cast<const float4*>(
                inp + (size_t)row * DIM);
            ull best = ~0ull;
            auto recheck = [&](int k) {
                const float4* ep = reinterpret_cast<const float4*>(
                    emb + (size_t)k * DIM);
                float c0 = 0.f, c1 = 0.f;
                #pragma unroll
                for (int i = 0; i < 16; i++) {
                    float4 xv = xp[i], ev = ep[i];
                    c0 = fmaf(xv.x, ev.x, c0);
                    c1 = fmaf(xv.y, ev.y, c1);
                    c0 = fmaf(xv.z, ev.z, c0);
                    c1 = fmaf(xv.w, ev.w, c1);
                }
                float c  = c0 + c1;
                float t  = tA + sbv[k];       // fl(A + b_k)
                float dd = t - 2.0f * c;      // fl(t - 2c)
                ull key = ((ull)ord32(dd) << 32) | (unsigned)k;
                if (key < best) best = key;
            };
            int n = cnt[prow];
            if (n <= SLOTS) {
                for (int p = part; p < n; p += 8)
                    recheck(list[prow * SLOTS + p]);
            } else {
                for (int k = part; k < KC; k += 8)    // safety net (~never)
                    recheck(k);
            }
            #pragma unroll
            for (int off = 4; off > 0; off >>= 1) {
                ull o = __shfl_xor_sync(0xFFFFFFFFu, best, off, 8);
                best = (o < best) ? o : best;
            }
            const int bik = (int)(unsigned)(best & 0xFFFFFFFFull);

            if (part == 0) {
                out[2 + NQ + row] = (float)bik;
                atomicAdd(&g_hist[bik], 1);
            }
            const float4* xq = reinterpret_cast<const float4*>(
                inp + (size_t)row * DIM + part * 8);
            const float4* eq = reinterpret_cast<const float4*>(
                emb + (size_t)bik * DIM + part * 8);
            float* q = out + 1 + (size_t)row * DIM + part * 8;  // 4B-aligned
            float sse = 0.f;
            #pragma unroll
            for (int i = 0; i < 2; i++) {
                float4 xv = xq[i], ev = eq[i];
                float d0 = ev.x - xv.x, d1 = ev.y - xv.y;
                float d2 = ev.z - xv.z, d3 = ev.w - xv.w;
                q[4*i+0] = xv.x + d0;                 // fl(x + fl(q-x))
                q[4*i+1] = xv.y + d1;
                q[4*i+2] = xv.z + d2;
                q[4*i+3] = xv.w + d3;
                sse += d0*d0 + d1*d1 + d2*d2 + d3*d3;
            }
            sse += __shfl_xor_sync(0xFFFFFFFFu, sse, 1, 8);
            sse += __shfl_xor_sync(0xFFFFFFFFu, sse, 2, 8);
            sse += __shfl_xor_sync(0xFFFFFFFFu, sse, 4, 8);
            if (part == 0) atomicAdd(&g_sse, (double)sse);
        }
    }

    // ---- last CTA finalizes loss & perplexity -------------------------------
    __threadfence();
    __syncthreads();
    __shared__ unsigned s_last;
    if (tid == 0)
        s_last = (atomicAdd(&g_done, 1u) == GRID - 1u) ? 1u : 0u;
    __syncthreads();
    if (s_last) {
        __threadfence();
        __shared__ float red[THREADS];
        float acc2 = 0.f;
        for (int b = tid; b < KC; b += THREADS) {
            float pb = (float)g_hist[b] * (1.0f / (float)NROWS);
            acc2 += pb * logf(pb + 1e-10f);
        }
        red[tid] = acc2;
        __syncthreads();
        for (int off = THREADS / 2; off > 0; off >>= 1) {
            if (tid < off) red[tid] += red[tid + off];
            __syncthreads();
        }
        if (tid == 0) {
            out[0]      = (float)(1.25 * (g_sse * (1.0 / (double)NQ)));
            out[1 + NQ] = expf(-red[0]);
        }
    }
}

extern "C" void kernel_launch(void* const* d_in, const int* in_sizes, int n_in,
                              void* d_out, int out_size)
{
    const float* inp = (const float*)d_in[0];
    const float* emb = (const float*)d_in[1];
    if (n_in >= 2 && in_sizes[0] == KC * DIM) {
        const float* t = inp; inp = emb; emb = t;
    }
    float* out = (float*)d_out;

    cudaFuncSetAttribute(vq_h2_kernel,
                         cudaFuncAttributeMaxDynamicSharedMemorySize,
                         SMEM_TOTAL);

    prep_kernel<<<4, 128>>>(emb);
    vq_h2_kernel<<<GRID, THREADS, SMEM_TOTAL>>>(inp, emb, out);
}

// round 15
// speedup vs baseline: 5.7934x; 5.7934x over previous
#include <cuda_runtime.h>
#include <math.h>

#define NROWS   65536
#define DIM     64
#define KC      512
#define NQ      (NROWS*DIM)
#define THREADS 512
#define MTILE   64
#define NTILES  (NROWS/MTILE)    // 1024
#define GRID    148
#define XTS     66               // padded X^T row stride (floats, even)

// smem byte offsets
#define SMO_ET   0                        // E^T: 64 x 512 f32 = 131072 B
#define SMO_XT   131072                   // X^T: 64 x 66 f32  = 16896 B
#define SMO_SB   147968                   // 512 f32 code norms
#define SMO_SA   150016                   // 64 f32 row norms
#define SMO_KEYS 150272                   // 64 u64 argmin keys
#define SMO_STG  150784                   // 2 x 16384 B X staging (cp.async)
#define SMEM_TOTAL 183552

// Output: [0] loss | [1..NQ] quantized_st (base out+1, 4B-aligned) |
//         [1+NQ] perplexity | [2+NQ..] indices (as float)

typedef unsigned long long ull;

__device__ float  g_ET[DIM*KC];     // E^T [d][k]
__device__ float  g_sb[KC];
__device__ int    g_hist[KC];
__device__ double g_sse;
__device__ unsigned g_done;

__device__ __forceinline__ ull splat2(float v) {
    ull r; asm("mov.b64 %0, {%1, %1};" : "=l"(r) : "f"(v)); return r;
}
__device__ __forceinline__ void upk2(ull v, float& lo, float& hi) {
    asm("mov.b64 {%0, %1}, %2;" : "=f"(lo), "=f"(hi) : "l"(v));
}
__device__ __forceinline__ ull fma2(ull a, ull b, ull c) {
    ull d; asm("fma.rn.f32x2 %0, %1, %2, %3;" : "=l"(d) : "l"(a), "l"(b), "l"(c));
    return d;
}
// order-preserving float -> u32 (total order) for (dd, k) min keys
__device__ __forceinline__ unsigned ord32(float f) {
    unsigned u = __float_as_uint(f);
    return (u & 0x80000000u) ? ~u : (u | 0x80000000u);
}
__device__ __forceinline__ void cp_async16(void* sptr, const void* gptr) {
    unsigned sa = (unsigned)__cvta_generic_to_shared(sptr);
    asm volatile("cp.async.ca.shared.global [%0], [%1], 16;"
                 :: "r"(sa), "l"(gptr) : "memory");
}

// ---- prep: E^T image + exact code norms + zero globals ----------------------
__global__ void prep_kernel(const float* __restrict__ emb) {
    int k = blockIdx.x * blockDim.x + threadIdx.x;
    if (k >= KC) return;
    if (k == 0) { g_sse = 0.0; g_done = 0u; }
    g_hist[k] = 0;

    const float* e = emb + (size_t)k * DIM;
    float b0 = 0.f, b1 = 0.f;
    #pragma unroll
    for (int i = 0; i < DIM; i += 2) {
        b0 = fmaf(e[i],     e[i],     b0);
        b1 = fmaf(e[i + 1], e[i + 1], b1);
    }
    g_sb[k] = b0 + b1;
    #pragma unroll
    for (int d = 0; d < DIM; d++)
        g_ET[d * KC + k] = e[d];
}

// -----------------------------------------------------------------------------
// Persistent GEMM-tiled VQ (R9 mainloop) + cp.async-pipelined X staging.
// 64-row x 512-code tiles, 512 threads, 8 rows x 8 codes per thread (f32x2).
// Exact JAX argmin: d_k = fl( fl(A + b_k) - 2*c_k ), first-index tie via
// (dd,k) min-key.
// -----------------------------------------------------------------------------
__global__ void __launch_bounds__(THREADS, 1)
vq_gemm_kernel(const float* __restrict__ inp,
               const float* __restrict__ emb,
               float* __restrict__ out)
{
    extern __shared__ char smc[];
    float* ET   = reinterpret_cast<float*>(smc + SMO_ET);
    float* XT   = reinterpret_cast<float*>(smc + SMO_XT);
    float* sbv  = reinterpret_cast<float*>(smc + SMO_SB);
    float* sA   = reinterpret_cast<float*>(smc + SMO_SA);
    ull*   keys = reinterpret_cast<ull*>(smc + SMO_KEYS);
    float* STG  = reinterpret_cast<float*>(smc + SMO_STG);

    const int tid  = threadIdx.x;
    const int lane = tid & 31;
    const int rp   = tid >> 6;    // row-group 0..7 (8 rows each)
    const int cg   = tid & 63;    // code lane: codes cg + 64*j

    // one-time smem fill: E^T + code norms
    for (int i = tid; i < DIM * KC / 4; i += THREADS)
        reinterpret_cast<float4*>(ET)[i] =
            reinterpret_cast<const float4*>(g_ET)[i];
    for (int i = tid; i < KC; i += THREADS) sbv[i] = g_sb[i];

    // prefetch first tile's X panel (16KB, coalesced; 2x16B per thread)
    {
        const char* g = reinterpret_cast<const char*>(
            inp + (size_t)blockIdx.x * MTILE * DIM) + tid * 32;
        char* s = smc + SMO_STG + tid * 32;
        cp_async16(s,      g);
        cp_async16(s + 16, g + 16);
        asm volatile("cp.async.commit_group;" ::: "memory");
    }

    int buf = 0;
    for (int tile = blockIdx.x; tile < NTILES; tile += GRID) {
        // prefetch NEXT tile into the other buffer (clamped; redundant if last)
        {
            int nt = tile + GRID; if (nt >= NTILES) nt = tile;
            const char* g = reinterpret_cast<const char*>(
                inp + (size_t)nt * MTILE * DIM) + tid * 32;
            char* s = smc + SMO_STG + (buf ^ 1) * 16384 + tid * 32;
            cp_async16(s,      g);
            cp_async16(s + 16, g + 16);
            asm volatile("cp.async.commit_group;" ::: "memory");
        }
        asm volatile("cp.async.wait_group 1;" ::: "memory");  // cur buf ready
        __syncthreads();   // staging visible + prior tile's XT/keys reads done

        const float* sx = STG + buf * 4096;   // cur staged X panel (64x64)

        // ---- prologue: 64 threads, one row each (exact A order preserved) --
        if (tid < MTILE) {
            const float4* xp = reinterpret_cast<const float4*>(sx + tid * DIM);
            float a0 = 0.f, a1 = 0.f;
            #pragma unroll
            for (int i = 0; i < 16; i++) {
                float4 v = xp[i];
                XT[(4 * i + 0) * XTS + tid] = v.x;
                XT[(4 * i + 1) * XTS + tid] = v.y;
                XT[(4 * i + 2) * XTS + tid] = v.z;
                XT[(4 * i + 3) * XTS + tid] = v.w;
                a0 = fmaf(v.x, v.x, a0);
                a1 = fmaf(v.y, v.y, a1);
                a0 = fmaf(v.z, v.z, a0);
                a1 = fmaf(v.w, v.w, a1);
            }
            sA[tid]   = a0 + a1;
            keys[tid] = ~0ull;
        }
        __syncthreads();

        // ---- mainloop (identical to R9): acc[i2][j] -------------------------
        ull acc[4][8];
        #pragma unroll
        for (int i2 = 0; i2 < 4; i2++)
            #pragma unroll
            for (int j = 0; j < 8; j++) acc[i2][j] = 0ull;

        const float* ETc = ET + cg;
        const float* XTr = XT + rp * 8;
        #pragma unroll 4
        for (int d = 0; d < DIM; d++) {
            ull x2[4];
            #pragma unroll
            for (int i2 = 0; i2 < 4; i2++)
                x2[i2] = *reinterpret_cast<const ull*>(XTr + d * XTS + 2 * i2);
            #pragma unroll
            for (int j = 0; j < 8; j++) {
                ull es = splat2(ETc[d * KC + 64 * j]);
                acc[0][j] = fma2(x2[0], es, acc[0][j]);
                acc[1][j] = fma2(x2[1], es, acc[1][j]);
                acc[2][j] = fma2(x2[2], es, acc[2][j]);
                acc[3][j] = fma2(x2[3], es, acc[3][j]);
            }
        }

        // ---- per-row local argmin keys over this thread's 8 codes ----------
        ull lkey[8];
        #pragma unroll
        for (int i = 0; i < 8; i++) lkey[i] = ~0ull;
        #pragma unroll
        for (int i2 = 0; i2 < 4; i2++) {
            float tA0 = sA[rp * 8 + 2 * i2];
            float tA1 = sA[rp * 8 + 2 * i2 + 1];
            #pragma unroll
            for (int j = 0; j < 8; j++) {
                int   k = cg + 64 * j;
                float b = sbv[k];
                float clo, chi;
                upk2(acc[i2][j], clo, chi);
                float t0  = tA0 + b;              // fl(A + b_k)
                float dd0 = t0 - 2.0f * clo;      // fl(t - 2c)
                ull  k0 = ((ull)ord32(dd0) << 32) | (unsigned)k;
                if (k0 < lkey[2 * i2]) lkey[2 * i2] = k0;
                float t1  = tA1 + b;
                float dd1 = t1 - 2.0f * chi;
                ull  k1 = ((ull)ord32(dd1) << 32) | (unsigned)k;
                if (k1 < lkey[2 * i2 + 1]) lkey[2 * i2 + 1] = k1;
            }
        }
        #pragma unroll
        for (int i = 0; i < 8; i++) {
            ull v = lkey[i];
            #pragma unroll
            for (int off = 16; off > 0; off >>= 1) {
                ull o = __shfl_xor_sync(0xFFFFFFFFu, v, off);
                v = (o < v) ? o : v;
            }
            if (lane == 0) atomicMin(&keys[rp * 8 + i], v);
        }
        __syncthreads();

        // ---- winners: 64 threads finish one row each (x from staging) ------
        if (tid < MTILE) {
            const int row = tile * MTILE + tid;
            const int bik = (int)(unsigned)(keys[tid] & 0xFFFFFFFFull);

            out[2 + NQ + row] = (float)bik;
            atomicAdd(&g_hist[bik], 1);

            const float4* xp = reinterpret_cast<const float4*>(sx + tid * DIM);
            const float4* ep = reinterpret_cast<const float4*>(
                emb + (size_t)bik * DIM);
            float* q = out + 1 + (size_t)row * DIM;  // base == 4 (mod 16) B

            float qs[DIM];
            float sse = 0.f;
            #pragma unroll
            for (int i = 0; i < 16; i++) {
                float4 xv = xp[i], ev = ep[i];
                float d0 = ev.x - xv.x, d1 = ev.y - xv.y;
                float d2 = ev.z - xv.z, d3 = ev.w - xv.w;
                qs[4*i]   = xv.x + d0;               // fl(x + fl(q-x))
                qs[4*i+1] = xv.y + d1;
                qs[4*i+2] = xv.z + d2;
                qs[4*i+3] = xv.w + d3;
                sse += d0*d0 + d1*d1 + d2*d2 + d3*d3;
            }
            q[0] = qs[0]; q[1] = qs[1]; q[2] = qs[2];
            float4* q4 = reinterpret_cast<float4*>(q + 3);
            #pragma unroll
            for (int i = 0; i < 15; i++)
                q4[i] = make_float4(qs[3+4*i], qs[4+4*i], qs[5+4*i], qs[6+4*i]);
            q[63] = qs[63];

            #pragma unroll
            for (int off = 16; off > 0; off >>= 1)
                sse += __shfl_xor_sync(0xFFFFFFFFu, sse, off);
            if (lane == 0) atomicAdd(&g_sse, (double)sse);
        }
        buf ^= 1;
    }

    // ---- last CTA finalizes loss & perplexity -------------------------------
    asm volatile("cp.async.wait_group 0;" ::: "memory");
    __threadfence();
    __syncthreads();
    __shared__ unsigned s_last;
    if (tid == 0)
        s_last = (atomicAdd(&g_done, 1u) == GRID - 1u) ? 1u : 0u;
    __syncthreads();
    if (s_last) {
        __threadfence();
        __shared__ float red[THREADS];
        float acc = 0.f;
        for (int b = tid; b < KC; b += THREADS) {
            float pb = (float)g_hist[b] * (1.0f / (float)NROWS);
            acc += pb * logf(pb + 1e-10f);
        }
        red[tid] = acc;
        __syncthreads();
        for (int off = THREADS / 2; off > 0; off >>= 1) {
            if (tid < off) red[tid] += red[tid + off];
            __syncthreads();
        }
        if (tid == 0) {
            out[0]      = (float)(1.25 * (g_sse * (1.0 / (double)NQ)));
            out[1 + NQ] = expf(-red[0]);
        }
    }
}

extern "C" void kernel_launch(void* const* d_in, const int* in_sizes, int n_in,
                              void* d_out, int out_size)
{
    const float* inp = (const float*)d_in[0];
    const float* emb = (const float*)d_in[1];
    if (n_in >= 2 && in_sizes[0] == KC * DIM) {
        const float* t = inp; inp = emb; emb = t;
    }
    float* out = (float*)d_out;

    cudaFuncSetAttribute(vq_gemm_kernel,
                         cudaFuncAttributeMaxDynamicSharedMemorySize,
                         SMEM_TOTAL);

    prep_kernel<<<4, 128>>>(emb);
    vq_gemm_kernel<<<GRID, THREADS, SMEM_TOTAL>>>(inp, emb, out);
}

// round 16
// speedup vs baseline: 5.8889x; 1.0165x over previous
#include <cuda_runtime.h>
#include <math.h>

#define NROWS   65536
#define DIM     64
#define KC      512
#define NQ      (NROWS*DIM)
#define THREADS 512
#define MTILE   64
#define NTILES  (NROWS/MTILE)    // 1024
#define GRID    148
#define XTS     66               // padded X^T row stride (floats, even)

// smem byte offsets
#define SMO_ET   0                        // E^T: 64 x 512 f32 = 131072 B
#define SMO_XT   131072                   // X^T: 64 x 66 f32  = 16896 B
#define SMO_SB   147968                   // 512 f32 code norms
#define SMO_SA   150016                   // 64 f32 row norms
#define SMO_KEYS 150272                   // 64 u64 argmin keys
#define SMO_STG  150784                   // 2 x 16384 B X staging (cp.async)
#define SMEM_TOTAL 183552

// Output: [0] loss | [1..NQ] quantized_st (base out+1, 4B-aligned) |
//         [1+NQ] perplexity | [2+NQ..] indices (as float)

typedef unsigned long long ull;

__device__ float  g_ET[DIM*KC];     // E^T [d][k]
__device__ float  g_sb[KC];
__device__ int    g_hist[KC];
__device__ double g_sse;
__device__ unsigned g_done;

__device__ __forceinline__ ull splat2(float v) {
    ull r; asm("mov.b64 %0, {%1, %1};" : "=l"(r) : "f"(v)); return r;
}
__device__ __forceinline__ void upk2(ull v, float& lo, float& hi) {
    asm("mov.b64 {%0, %1}, %2;" : "=f"(lo), "=f"(hi) : "l"(v));
}
__device__ __forceinline__ ull fma2(ull a, ull b, ull c) {
    ull d; asm("fma.rn.f32x2 %0, %1, %2, %3;" : "=l"(d) : "l"(a), "l"(b), "l"(c));
    return d;
}
// order-preserving float -> u32 (total order) for (dd, k) min keys
__device__ __forceinline__ unsigned ord32(float f) {
    unsigned u = __float_as_uint(f);
    return (u & 0x80000000u) ? ~u : (u | 0x80000000u);
}
__device__ __forceinline__ void cp_async16(void* sptr, const void* gptr) {
    unsigned sa = (unsigned)__cvta_generic_to_shared(sptr);
    asm volatile("cp.async.ca.shared.global [%0], [%1], 16;"
                 :: "r"(sa), "l"(gptr) : "memory");
}

// ---- prep: E^T image + exact code norms + zero globals ----------------------
__global__ void prep_kernel(const float* __restrict__ emb) {
    int k = blockIdx.x * blockDim.x + threadIdx.x;
    if (k >= KC) return;
    if (k == 0) { g_sse = 0.0; g_done = 0u; }
    g_hist[k] = 0;

    const float* e = emb + (size_t)k * DIM;
    float b0 = 0.f, b1 = 0.f;
    #pragma unroll
    for (int i = 0; i < DIM; i += 2) {
        b0 = fmaf(e[i],     e[i],     b0);
        b1 = fmaf(e[i + 1], e[i + 1], b1);
    }
    g_sb[k] = b0 + b1;
    #pragma unroll
    for (int d = 0; d < DIM; d++)
        g_ET[d * KC + k] = e[d];
}

// -----------------------------------------------------------------------------
// Persistent GEMM-tiled VQ (R9 mainloop) + cp.async-pipelined X staging.
// RACE FIX vs R15: a barrier at the top of the tile loop orders the previous
// tile's staging-buffer READS before this iteration's cp.async WRITES into the
// same buffer (write target at tile N+1 == read buffer of tile N).
// Exact JAX argmin: d_k = fl( fl(A + b_k) - 2*c_k ), first-index tie via
// (dd,k) min-key.
// -----------------------------------------------------------------------------
__global__ void __launch_bounds__(THREADS, 1)
vq_gemm_kernel(const float* __restrict__ inp,
               const float* __restrict__ emb,
               float* __restrict__ out)
{
    extern __shared__ char smc[];
    float* ET   = reinterpret_cast<float*>(smc + SMO_ET);
    float* XT   = reinterpret_cast<float*>(smc + SMO_XT);
    float* sbv  = reinterpret_cast<float*>(smc + SMO_SB);
    float* sA   = reinterpret_cast<float*>(smc + SMO_SA);
    ull*   keys = reinterpret_cast<ull*>(smc + SMO_KEYS);
    float* STG  = reinterpret_cast<float*>(smc + SMO_STG);

    const int tid  = threadIdx.x;
    const int lane = tid & 31;
    const int rp   = tid >> 6;    // row-group 0..7 (8 rows each)
    const int cg   = tid & 63;    // code lane: codes cg + 64*j

    // one-time smem fill: E^T + code norms
    for (int i = tid; i < DIM * KC / 4; i += THREADS)
        reinterpret_cast<float4*>(ET)[i] =
            reinterpret_cast<const float4*>(g_ET)[i];
    for (int i = tid; i < KC; i += THREADS) sbv[i] = g_sb[i];

    // prefetch first tile's X panel (16KB, coalesced; 2x16B per thread)
    {
        const char* g = reinterpret_cast<const char*>(
            inp + (size_t)blockIdx.x * MTILE * DIM) + tid * 32;
        char* s = smc + SMO_STG + tid * 32;
        cp_async16(s,      g);
        cp_async16(s + 16, g + 16);
        asm volatile("cp.async.commit_group;" ::: "memory");
    }

    int buf = 0;
    for (int tile = blockIdx.x; tile < NTILES; tile += GRID) {
        // RACE FIX: all reads of buffer (buf^1) from the PREVIOUS tile must
        // complete before we overwrite it below.
        __syncthreads();

        // prefetch NEXT tile into the other buffer (clamped; redundant if last)
        {
            int nt = tile + GRID; if (nt >= NTILES) nt = tile;
            const char* g = reinterpret_cast<const char*>(
                inp + (size_t)nt * MTILE * DIM) + tid * 32;
            char* s = smc + SMO_STG + (buf ^ 1) * 16384 + tid * 32;
            cp_async16(s,      g);
            cp_async16(s + 16, g + 16);
            asm volatile("cp.async.commit_group;" ::: "memory");
        }
        asm volatile("cp.async.wait_group 1;" ::: "memory");  // cur buf ready
        __syncthreads();   // staging visible + prior tile's XT/keys reads done

        const float* sx = STG + buf * 4096;   // cur staged X panel (64x64)

        // ---- prologue: 64 threads, one row each (exact A order preserved) --
        if (tid < MTILE) {
            const float4* xp = reinterpret_cast<const float4*>(sx + tid * DIM);
            float a0 = 0.f, a1 = 0.f;
            #pragma unroll
            for (int i = 0; i < 16; i++) {
                float4 v = xp[i];
                XT[(4 * i + 0) * XTS + tid] = v.x;
                XT[(4 * i + 1) * XTS + tid] = v.y;
                XT[(4 * i + 2) * XTS + tid] = v.z;
                XT[(4 * i + 3) * XTS + tid] = v.w;
                a0 = fmaf(v.x, v.x, a0);
                a1 = fmaf(v.y, v.y, a1);
                a0 = fmaf(v.z, v.z, a0);
                a1 = fmaf(v.w, v.w, a1);
            }
            sA[tid]   = a0 + a1;
            keys[tid] = ~0ull;
        }
        __syncthreads();

        // ---- mainloop (identical to R9): acc[i2][j] -------------------------
        ull acc[4][8];
        #pragma unroll
        for (int i2 = 0; i2 < 4; i2++)
            #pragma unroll
            for (int j = 0; j < 8; j++) acc[i2][j] = 0ull;

        const float* ETc = ET + cg;
        const float* XTr = XT + rp * 8;
        #pragma unroll 4
        for (int d = 0; d < DIM; d++) {
            ull x2[4];
            #pragma unroll
            for (int i2 = 0; i2 < 4; i2++)
                x2[i2] = *reinterpret_cast<const ull*>(XTr + d * XTS + 2 * i2);
            #pragma unroll
            for (int j = 0; j < 8; j++) {
                ull es = splat2(ETc[d * KC + 64 * j]);
                acc[0][j] = fma2(x2[0], es, acc[0][j]);
                acc[1][j] = fma2(x2[1], es, acc[1][j]);
                acc[2][j] = fma2(x2[2], es, acc[2][j]);
                acc[3][j] = fma2(x2[3], es, acc[3][j]);
            }
        }

        // ---- per-row local argmin keys over this thread's 8 codes ----------
        ull lkey[8];
        #pragma unroll
        for (int i = 0; i < 8; i++) lkey[i] = ~0ull;
        #pragma unroll
        for (int i2 = 0; i2 < 4; i2++) {
            float tA0 = sA[rp * 8 + 2 * i2];
            float tA1 = sA[rp * 8 + 2 * i2 + 1];
            #pragma unroll
            for (int j = 0; j < 8; j++) {
                int   k = cg + 64 * j;
                float b = sbv[k];
                float clo, chi;
                upk2(acc[i2][j], clo, chi);
                float t0  = tA0 + b;              // fl(A + b_k)
                float dd0 = t0 - 2.0f * clo;      // fl(t - 2c)
                ull  k0 = ((ull)ord32(dd0) << 32) | (unsigned)k;
                if (k0 < lkey[2 * i2]) lkey[2 * i2] = k0;
                float t1  = tA1 + b;
                float dd1 = t1 - 2.0f * chi;
                ull  k1 = ((ull)ord32(dd1) << 32) | (unsigned)k;
                if (k1 < lkey[2 * i2 + 1]) lkey[2 * i2 + 1] = k1;
            }
        }
        #pragma unroll
        for (int i = 0; i < 8; i++) {
            ull v = lkey[i];
            #pragma unroll
            for (int off = 16; off > 0; off >>= 1) {
                ull o = __shfl_xor_sync(0xFFFFFFFFu, v, off);
                v = (o < v) ? o : v;
            }
            if (lane == 0) atomicMin(&keys[rp * 8 + i], v);
        }
        __syncthreads();

        // ---- winners: 64 threads finish one row each (x from staging) ------
        if (tid < MTILE) {
            const int row = tile * MTILE + tid;
            const int bik = (int)(unsigned)(keys[tid] & 0xFFFFFFFFull);

            out[2 + NQ + row] = (float)bik;
            atomicAdd(&g_hist[bik], 1);

            const float4* xp = reinterpret_cast<const float4*>(sx + tid * DIM);
            const float4* ep = reinterpret_cast<const float4*>(
                emb + (size_t)bik * DIM);
            float* q = out + 1 + (size_t)row * DIM;  // base == 4 (mod 16) B

            float qs[DIM];
            float sse = 0.f;
            #pragma unroll
            for (int i = 0; i < 16; i++) {
                float4 xv = xp[i], ev = ep[i];
                float d0 = ev.x - xv.x, d1 = ev.y - xv.y;
                float d2 = ev.z - xv.z, d3 = ev.w - xv.w;
                qs[4*i]   = xv.x + d0;               // fl(x + fl(q-x))
                qs[4*i+1] = xv.y + d1;
                qs[4*i+2] = xv.z + d2;
                qs[4*i+3] = xv.w + d3;
                sse += d0*d0 + d1*d1 + d2*d2 + d3*d3;
            }
            q[0] = qs[0]; q[1] = qs[1]; q[2] = qs[2];
            float4* q4 = reinterpret_cast<float4*>(q + 3);
            #pragma unroll
            for (int i = 0; i < 15; i++)
                q4[i] = make_float4(qs[3+4*i], qs[4+4*i], qs[5+4*i], qs[6+4*i]);
            q[63] = qs[63];

            #pragma unroll
            for (int off = 16; off > 0; off >>= 1)
                sse += __shfl_xor_sync(0xFFFFFFFFu, sse, off);
            if (lane == 0) atomicAdd(&g_sse, (double)sse);
        }
        buf ^= 1;
    }

    // ---- last CTA finalizes loss & perplexity -------------------------------
    asm volatile("cp.async.wait_group 0;" ::: "memory");
    __threadfence();
    __syncthreads();
    __shared__ unsigned s_last;
    if (tid == 0)
        s_last = (atomicAdd(&g_done, 1u) == GRID - 1u) ? 1u : 0u;
    __syncthreads();
    if (s_last) {
        __threadfence();
        __shared__ float red[THREADS];
        float acc = 0.f;
        for (int b = tid; b < KC; b += THREADS) {
            float pb = (float)g_hist[b] * (1.0f / (float)NROWS);
            acc += pb * logf(pb + 1e-10f);
        }
        red[tid] = acc;
        __syncthreads();
        for (int off = THREADS / 2; off > 0; off >>= 1) {
            if (tid < off) red[tid] += red[tid + off];
            __syncthreads();
        }
        if (tid == 0) {
            out[0]      = (float)(1.25 * (g_sse * (1.0 / (double)NQ)));
            out[1 + NQ] = expf(-red[0]);
        }
    }
}

extern "C" void kernel_launch(void* const* d_in, const int* in_sizes, int n_in,
                              void* d_out, int out_size)
{
    const float* inp = (const float*)d_in[0];
    const float* emb = (const float*)d_in[1];
    if (n_in >= 2 && in_sizes[0] == KC * DIM) {
        const float* t = inp; inp = emb; emb = t;
    }
    float* out = (float*)d_out;

    cudaFuncSetAttribute(vq_gemm_kernel,
                         cudaFuncAttributeMaxDynamicSharedMemorySize,
                         SMEM_TOTAL);

    prep_kernel<<<4, 128>>>(emb);
    vq_gemm_kernel<<<GRID, THREADS, SMEM_TOTAL>>>(inp, emb, out);
}

// round 17
// speedup vs baseline: 5.9133x; 1.0041x over previous
#include <cuda_runtime.h>
#include <math.h>

#define NROWS   65536
#define DIM     64
#define KC      512
#define NQ      (NROWS*DIM)
#define THREADS 512
#define MTILE   64
#define NTILES  (NROWS/MTILE)    // 1024
#define GRID    148
#define XTS     66               // padded X^T row stride (floats, even)

// smem byte offsets
#define SMO_ET   0                        // E^T: 64 x 512 f32 = 131072 B
#define SMO_XT   131072                   // X^T: 64 x 66 f32  = 16896 B
#define SMO_SB   147968                   // 512 f32 code norms
#define SMO_SA   150016                   // 64 f32 row norms
#define SMO_KEYS 150272                   // 64 u64 argmin keys
#define SMO_STG  150784                   // 2 x 16384 B X staging (cp.async)
#define SMEM_TOTAL 183552

// Output: [0] loss | [1..NQ] quantized_st (base out+1, 4B-aligned) |
//         [1+NQ] perplexity | [2+NQ..] indices (as float)

typedef unsigned long long ull;

__device__ float  g_ET[DIM*KC];     // E^T [d][k]
__device__ float  g_sb[KC];
__device__ int    g_hist[KC];
__device__ double g_sse;
__device__ unsigned g_done;

__device__ __forceinline__ ull splat2(float v) {
    ull r; asm("mov.b64 %0, {%1, %1};" : "=l"(r) : "f"(v)); return r;
}
__device__ __forceinline__ void upk2(ull v, float& lo, float& hi) {
    asm("mov.b64 {%0, %1}, %2;" : "=f"(lo), "=f"(hi) : "l"(v));
}
__device__ __forceinline__ ull fma2(ull a, ull b, ull c) {
    ull d; asm("fma.rn.f32x2 %0, %1, %2, %3;" : "=l"(d) : "l"(a), "l"(b), "l"(c));
    return d;
}
// order-preserving float -> u32 (total order) for (dd, k) min keys
__device__ __forceinline__ unsigned ord32(float f) {
    unsigned u = __float_as_uint(f);
    return (u & 0x80000000u) ? ~u : (u | 0x80000000u);
}
__device__ __forceinline__ void cp_async16(void* sptr, const void* gptr) {
    unsigned sa = (unsigned)__cvta_generic_to_shared(sptr);
    asm volatile("cp.async.ca.shared.global [%0], [%1], 16;"
                 :: "r"(sa), "l"(gptr) : "memory");
}

// ---- prep: E^T image + exact code norms + zero globals ----------------------
__global__ void prep_kernel(const float* __restrict__ emb) {
    int k = blockIdx.x * blockDim.x + threadIdx.x;
    if (k >= KC) return;
    if (k == 0) { g_sse = 0.0; g_done = 0u; }
    g_hist[k] = 0;

    const float* e = emb + (size_t)k * DIM;
    float b0 = 0.f, b1 = 0.f;
    #pragma unroll
    for (int i = 0; i < DIM; i += 2) {
        b0 = fmaf(e[i],     e[i],     b0);
        b1 = fmaf(e[i + 1], e[i + 1], b1);
    }
    g_sb[k] = b0 + b1;
    #pragma unroll
    for (int d = 0; d < DIM; d++)
        g_ET[d * KC + k] = e[d];
}

// -----------------------------------------------------------------------------
// Persistent GEMM-tiled VQ: 64-row x 512-code tiles, 512 threads,
// 16 rows x 4 codes per thread (f32x2 row-pairs) — 4 E-splats/d instead of 8.
// cp.async X staging (double-buffered, race-fixed). Exact JAX argmin:
//   d_k = fl( fl(A + b_k) - 2*c_k ), first-index tie via (dd,k) min-key.
// Per-(row,code) accumulation chain is d-ascending, identical to R9/R16 ->
// bit-identical results.
// -----------------------------------------------------------------------------
__global__ void __launch_bounds__(THREADS, 1)
vq_gemm_kernel(const float* __restrict__ inp,
               const float* __restrict__ emb,
               float* __restrict__ out)
{
    extern __shared__ char smc[];
    float* ET   = reinterpret_cast<float*>(smc + SMO_ET);
    float* XT   = reinterpret_cast<float*>(smc + SMO_XT);
    float* sbv  = reinterpret_cast<float*>(smc + SMO_SB);
    float* sA   = reinterpret_cast<float*>(smc + SMO_SA);
    ull*   keys = reinterpret_cast<ull*>(smc + SMO_KEYS);
    float* STG  = reinterpret_cast<float*>(smc + SMO_STG);

    const int tid  = threadIdx.x;
    const int lane = tid & 31;
    const int rg   = tid >> 7;    // row-group 0..3 (16 rows each)
    const int cg   = tid & 127;   // code lane: codes cg + 128*j

    // one-time smem fill: E^T + code norms
    for (int i = tid; i < DIM * KC / 4; i += THREADS)
        reinterpret_cast<float4*>(ET)[i] =
            reinterpret_cast<const float4*>(g_ET)[i];
    for (int i = tid; i < KC; i += THREADS) sbv[i] = g_sb[i];

    // prefetch first tile's X panel (16KB, coalesced; 2x16B per thread)
    {
        const char* g = reinterpret_cast<const char*>(
            inp + (size_t)blockIdx.x * MTILE * DIM) + tid * 32;
        char* s = smc + SMO_STG + tid * 32;
        cp_async16(s,      g);
        cp_async16(s + 16, g + 16);
        asm volatile("cp.async.commit_group;" ::: "memory");
    }

    int buf = 0;
    for (int tile = blockIdx.x; tile < NTILES; tile += GRID) {
        // RACE FIX: all reads of buffer (buf^1) from the PREVIOUS tile must
        // complete before we overwrite it below.
        __syncthreads();

        // prefetch NEXT tile into the other buffer (clamped; redundant if last)
        {
            int nt = tile + GRID; if (nt >= NTILES) nt = tile;
            const char* g = reinterpret_cast<const char*>(
                inp + (size_t)nt * MTILE * DIM) + tid * 32;
            char* s = smc + SMO_STG + (buf ^ 1) * 16384 + tid * 32;
            cp_async16(s,      g);
            cp_async16(s + 16, g + 16);
            asm volatile("cp.async.commit_group;" ::: "memory");
        }
        asm volatile("cp.async.wait_group 1;" ::: "memory");  // cur buf ready
        __syncthreads();   // staging visible + prior tile's XT/keys reads done

        const float* sx = STG + buf * 4096;   // cur staged X panel (64x64)

        // ---- prologue: 64 threads, one row each (exact A order preserved) --
        if (tid < MTILE) {
            const float4* xp = reinterpret_cast<const float4*>(sx + tid * DIM);
            float a0 = 0.f, a1 = 0.f;
            #pragma unroll
            for (int i = 0; i < 16; i++) {
                float4 v = xp[i];
                XT[(4 * i + 0) * XTS + tid] = v.x;
                XT[(4 * i + 1) * XTS + tid] = v.y;
                XT[(4 * i + 2) * XTS + tid] = v.z;
                XT[(4 * i + 3) * XTS + tid] = v.w;
                a0 = fmaf(v.x, v.x, a0);
                a1 = fmaf(v.y, v.y, a1);
                a0 = fmaf(v.z, v.z, a0);
                a1 = fmaf(v.w, v.w, a1);
            }
            sA[tid]   = a0 + a1;
            keys[tid] = ~0ull;
        }
        __syncthreads();

        // ---- mainloop: acc[i2][j] = c(rows rg*16+2i2,+1; code cg+128j) -----
        ull acc[8][4];
        #pragma unroll
        for (int i2 = 0; i2 < 8; i2++)
            #pragma unroll
            for (int j = 0; j < 4; j++) acc[i2][j] = 0ull;

        const float* ETc = ET + cg;
        const float* XTr = XT + rg * 16;
        #pragma unroll 2
        for (int d = 0; d < DIM; d++) {
            ull x2[8];
            #pragma unroll
            for (int i2 = 0; i2 < 8; i2++)   // broadcast LDS.64 (lane-invariant)
                x2[i2] = *reinterpret_cast<const ull*>(XTr + d * XTS + 2 * i2);
            const float* Ed = ETc + d * KC;
            ull e0 = splat2(Ed[0]);
            ull e1 = splat2(Ed[128]);
            ull e2 = splat2(Ed[256]);
            ull e3 = splat2(Ed[384]);
            #pragma unroll
            for (int i2 = 0; i2 < 8; i2++) {
                acc[i2][0] = fma2(x2[i2], e0, acc[i2][0]);
                acc[i2][1] = fma2(x2[i2], e1, acc[i2][1]);
                acc[i2][2] = fma2(x2[i2], e2, acc[i2][2]);
                acc[i2][3] = fma2(x2[i2], e3, acc[i2][3]);
            }
        }

        // ---- per-row argmin keys over this thread's 4 codes ----------------
        #pragma unroll
        for (int i2 = 0; i2 < 8; i2++) {
            float tA0 = sA[rg * 16 + 2 * i2];
            float tA1 = sA[rg * 16 + 2 * i2 + 1];
            ull b0 = ~0ull, b1 = ~0ull;
            #pragma unroll
            for (int j = 0; j < 4; j++) {
                int   k = cg + 128 * j;
                float b = sbv[k];
                float clo, chi;
                upk2(acc[i2][j], clo, chi);
                float t0  = tA0 + b;              // fl(A + b_k)
                float dd0 = t0 - 2.0f * clo;      // fl(t - 2c)
                ull  k0 = ((ull)ord32(dd0) << 32) | (unsigned)k;
                if (k0 < b0) b0 = k0;
                float t1  = tA1 + b;
                float dd1 = t1 - 2.0f * chi;
                ull  k1 = ((ull)ord32(dd1) << 32) | (unsigned)k;
                if (k1 < b1) b1 = k1;
            }
            #pragma unroll
            for (int off = 16; off > 0; off >>= 1) {
                ull o0 = __shfl_xor_sync(0xFFFFFFFFu, b0, off);
                ull o1 = __shfl_xor_sync(0xFFFFFFFFu, b1, off);
                b0 = (o0 < b0) ? o0 : b0;
                b1 = (o1 < b1) ? o1 : b1;
            }
            if (lane == 0) {
                atomicMin(&keys[rg * 16 + 2 * i2],     b0);
                atomicMin(&keys[rg * 16 + 2 * i2 + 1], b1);
            }
        }
        __syncthreads();

        // ---- winners: 64 threads finish one row each (x from staging) ------
        if (tid < MTILE) {
            const int row = tile * MTILE + tid;
            const int bik = (int)(unsigned)(keys[tid] & 0xFFFFFFFFull);

            out[2 + NQ + row] = (float)bik;
            atomicAdd(&g_hist[bik], 1);

            const float4* xp = reinterpret_cast<const float4*>(sx + tid * DIM);
            const float4* ep = reinterpret_cast<const float4*>(
                emb + (size_t)bik * DIM);
            float* q = out + 1 + (size_t)row * DIM;  // base == 4 (mod 16) B

            float qs[DIM];
            float sse = 0.f;
            #pragma unroll
            for (int i = 0; i < 16; i++) {
                float4 xv = xp[i], ev = ep[i];
                float d0 = ev.x - xv.x, d1 = ev.y - xv.y;
                float d2 = ev.z - xv.z, d3 = ev.w - xv.w;
                qs[4*i]   = xv.x + d0;               // fl(x + fl(q-x))
                qs[4*i+1] = xv.y + d1;
                qs[4*i+2] = xv.z + d2;
                qs[4*i+3] = xv.w + d3;
                sse += d0*d0 + d1*d1 + d2*d2 + d3*d3;
            }
            q[0] = qs[0]; q[1] = qs[1]; q[2] = qs[2];
            float4* q4 = reinterpret_cast<float4*>(q + 3);
            #pragma unroll
            for (int i = 0; i < 15; i++)
                q4[i] = make_float4(qs[3+4*i], qs[4+4*i], qs[5+4*i], qs[6+4*i]);
            q[63] = qs[63];

            #pragma unroll
            for (int off = 16; off > 0; off >>= 1)
                sse += __shfl_xor_sync(0xFFFFFFFFu, sse, off);
            if (lane == 0) atomicAdd(&g_sse, (double)sse);
        }
        buf ^= 1;
    }

    // ---- last CTA finalizes loss & perplexity -------------------------------
    asm volatile("cp.async.wait_group 0;" ::: "memory");
    __threadfence();
    __syncthreads();
    __shared__ unsigned s_last;
    if (tid == 0)
        s_last = (atomicAdd(&g_done, 1u) == GRID - 1u) ? 1u : 0u;
    __syncthreads();
    if (s_last) {
        __threadfence();
        __shared__ float red[THREADS];
        float acc = 0.f;
        for (int b = tid; b < KC; b += THREADS) {
            float pb = (float)g_hist[b] * (1.0f / (float)NROWS);
            acc += pb * logf(pb + 1e-10f);
        }
        red[tid] = acc;
        __syncthreads();
        for (int off = THREADS / 2; off > 0; off >>= 1) {
            if (tid < off) red[tid] += red[tid + off];
            __syncthreads();
        }
        if (tid == 0) {
            out[0]      = (float)(1.25 * (g_sse * (1.0 / (double)NQ)));
            out[1 + NQ] = expf(-red[0]);
        }
    }
}

extern "C" void kernel_launch(void* const* d_in, const int* in_sizes, int n_in,
                              void* d_out, int out_size)
{
    const float* inp = (const float*)d_in[0];
    const float* emb = (const float*)d_in[1];
    if (n_in >= 2 && in_sizes[0] == KC * DIM) {
        const float* t = inp; inp = emb; emb = t;
    }
    float* out = (float*)d_out;

    cudaFuncSetAttribute(vq_gemm_kernel,
                         cudaFuncAttributeMaxDynamicSharedMemorySize,
                         SMEM_TOTAL);

    prep_kernel<<<4, 128>>>(emb);
    vq_gemm_kernel<<<GRID, THREADS, SMEM_TOTAL>>>(inp, emb, out);
}